// round 1
// baseline (speedup 1.0000x reference)
#include <cuda_runtime.h>
#include <cuda_bf16.h>
#include <math.h>

#define N_NODES 100000
#define N_EDGES 1600000
#define N_PAIRS 500000
#define D 128

// Scratch (device globals; no allocation allowed).
__device__ float g_deg[N_NODES];            // degree -> dinv (in place)
__device__ float g_t[(size_t)N_NODES * D];  // linear-transform output (per conv)
__device__ float g_acc[(size_t)N_NODES * D];// scatter-add accumulator (zeroed by finalize)
__device__ float g_h[(size_t)N_NODES * D];  // h1, then overwritten by h2

// ---------------------------------------------------------------------------
// degree kernels
// ---------------------------------------------------------------------------
__global__ void k_init_deg(float* deg) {
    int i = blockIdx.x * blockDim.x + threadIdx.x;
    if (i < N_NODES) deg[i] = 1.0f;  // self-loop
}

__global__ void k_deg(const int* __restrict__ dst, float* deg) {
    int e = blockIdx.x * blockDim.x + threadIdx.x;
    if (e < N_EDGES) atomicAdd(&deg[dst[e]], 1.0f);
}

__global__ void k_dinv(float* deg) {
    int i = blockIdx.x * blockDim.x + threadIdx.x;
    if (i < N_NODES) deg[i] = rsqrtf(deg[i]);
}

// ---------------------------------------------------------------------------
// GEMM: C[M,128] = A[M,128] @ W[128,128]
// 128x128 block tile, K-chunks of 32, 8x8 register micro-tile, 256 threads.
// ---------------------------------------------------------------------------
#define KC 32
__global__ __launch_bounds__(256, 2) void k_gemm(const float* __restrict__ A,
                                                 const float* __restrict__ W,
                                                 float* __restrict__ C, int M) {
    __shared__ float As[128][KC + 1];
    __shared__ float Ws[KC][D];

    int tid = threadIdx.x;
    int tx = tid & 15;        // 0..15 -> col group
    int ty = tid >> 4;        // 0..15 -> row group
    int row0 = blockIdx.x * 128;

    float acc[8][8];
#pragma unroll
    for (int i = 0; i < 8; i++)
#pragma unroll
        for (int j = 0; j < 8; j++) acc[i][j] = 0.0f;

    for (int k0 = 0; k0 < D; k0 += KC) {
        // load A tile: 128 rows x 32 cols = 1024 float4, 4 per thread
#pragma unroll
        for (int i = 0; i < 4; i++) {
            int f = tid + i * 256;          // 0..1023
            int r = f >> 3;                 // row (8 float4 per row)
            int c4 = f & 7;
            float4 v = make_float4(0.f, 0.f, 0.f, 0.f);
            int gr = row0 + r;
            if (gr < M) v = *(const float4*)&A[(size_t)gr * D + k0 + c4 * 4];
            As[r][c4 * 4 + 0] = v.x;
            As[r][c4 * 4 + 1] = v.y;
            As[r][c4 * 4 + 2] = v.z;
            As[r][c4 * 4 + 3] = v.w;
        }
        // load W tile: 32 rows x 128 cols = 1024 float4
#pragma unroll
        for (int i = 0; i < 4; i++) {
            int f = tid + i * 256;
            int r = f >> 5;                 // 32 float4 per row
            int c4 = f & 31;
            *(float4*)&Ws[r][c4 * 4] = *(const float4*)&W[(size_t)(k0 + r) * D + c4 * 4];
        }
        __syncthreads();

#pragma unroll
        for (int kk = 0; kk < KC; kk++) {
            float a[8], b[8];
#pragma unroll
            for (int i = 0; i < 8; i++) a[i] = As[ty * 8 + i][kk];
            float4 b0 = *(float4*)&Ws[kk][tx * 8];
            float4 b1 = *(float4*)&Ws[kk][tx * 8 + 4];
            b[0] = b0.x; b[1] = b0.y; b[2] = b0.z; b[3] = b0.w;
            b[4] = b1.x; b[5] = b1.y; b[6] = b1.z; b[7] = b1.w;
#pragma unroll
            for (int i = 0; i < 8; i++)
#pragma unroll
                for (int j = 0; j < 8; j++)
                    acc[i][j] = fmaf(a[i], b[j], acc[i][j]);
        }
        __syncthreads();
    }

#pragma unroll
    for (int i = 0; i < 8; i++) {
        int gr = row0 + ty * 8 + i;
        if (gr < M) {
            *(float4*)&C[(size_t)gr * D + tx * 8] =
                make_float4(acc[i][0], acc[i][1], acc[i][2], acc[i][3]);
            *(float4*)&C[(size_t)gr * D + tx * 8 + 4] =
                make_float4(acc[i][4], acc[i][5], acc[i][6], acc[i][7]);
        }
    }
}

// ---------------------------------------------------------------------------
// SpMM scatter: acc[dst] += t[src] * dinv[src] * dinv[dst]  (warp per edge)
// ---------------------------------------------------------------------------
__global__ __launch_bounds__(256) void k_spmm(const int* __restrict__ src,
                                              const int* __restrict__ dst,
                                              const float* __restrict__ dinv,
                                              const float* __restrict__ t,
                                              float* __restrict__ acc) {
    int e = (blockIdx.x * blockDim.x + threadIdx.x) >> 5;
    if (e >= N_EDGES) return;
    int lane = threadIdx.x & 31;
    int s = __ldg(&src[e]);
    int d = __ldg(&dst[e]);
    float nrm = __ldg(&dinv[s]) * __ldg(&dinv[d]);
    float4 v = *(const float4*)&t[(size_t)s * D + lane * 4];
    v.x *= nrm; v.y *= nrm; v.z *= nrm; v.w *= nrm;
    atomicAdd((float4*)&acc[(size_t)d * D + lane * 4], v);
}

// ---------------------------------------------------------------------------
// Finalize: h = act(acc + t*dinv^2 + bias); zero acc for next use/replay.
// One thread per float4 (N_NODES * 32 threads).
// ---------------------------------------------------------------------------
template <bool RELU>
__global__ __launch_bounds__(256) void k_finalize(const float* __restrict__ t,
                                                  float* __restrict__ acc,
                                                  const float* __restrict__ dinv,
                                                  const float* __restrict__ bias,
                                                  float* __restrict__ h) {
    int idx = blockIdx.x * blockDim.x + threadIdx.x;   // float4 index
    if (idx >= N_NODES * (D / 4)) return;
    int node = idx >> 5;             // D/4 = 32 float4 per node
    int q = idx & 31;
    float di = dinv[node];
    float s = di * di;
    float4 a = *(float4*)&acc[(size_t)idx * 4];
    float4 tv = *(const float4*)&t[(size_t)idx * 4];
    float4 b = *(const float4*)&bias[q * 4];
    float4 o;
    o.x = fmaf(tv.x, s, a.x) + b.x;
    o.y = fmaf(tv.y, s, a.y) + b.y;
    o.z = fmaf(tv.z, s, a.z) + b.z;
    o.w = fmaf(tv.w, s, a.w) + b.w;
    if (RELU) {
        o.x = fmaxf(o.x, 0.f); o.y = fmaxf(o.y, 0.f);
        o.z = fmaxf(o.z, 0.f); o.w = fmaxf(o.w, 0.f);
    }
    *(float4*)&h[(size_t)idx * 4] = o;
    *(float4*)&acc[(size_t)idx * 4] = make_float4(0.f, 0.f, 0.f, 0.f);
}

// ---------------------------------------------------------------------------
// Pair scores: out[p] = dot(h[a], h[b]); warp per pair; pos then neg.
// ---------------------------------------------------------------------------
__global__ __launch_bounds__(256) void k_pairs(const int* __restrict__ edges,
                                               const int* __restrict__ edges_neg,
                                               const float* __restrict__ h,
                                               float* __restrict__ out) {
    int p = (blockIdx.x * blockDim.x + threadIdx.x) >> 5;
    if (p >= 2 * N_PAIRS) return;
    int lane = threadIdx.x & 31;
    const int* e = (p < N_PAIRS) ? edges : edges_neg;
    int pp = (p < N_PAIRS) ? p : (p - N_PAIRS);
    int a = __ldg(&e[2 * pp]);
    int b = __ldg(&e[2 * pp + 1]);
    float4 va = *(const float4*)&h[(size_t)a * D + lane * 4];
    float4 vb = *(const float4*)&h[(size_t)b * D + lane * 4];
    float sum = va.x * vb.x + va.y * vb.y + va.z * vb.z + va.w * vb.w;
#pragma unroll
    for (int off = 16; off > 0; off >>= 1)
        sum += __shfl_xor_sync(0xFFFFFFFFu, sum, off);
    if (lane == 0) out[p] = sum;
}

// ---------------------------------------------------------------------------
// launch
// ---------------------------------------------------------------------------
extern "C" void kernel_launch(void* const* d_in, const int* in_sizes, int n_in,
                              void* d_out, int out_size) {
    const float* x     = (const float*)d_in[0];
    const float* W1    = (const float*)d_in[1];
    const float* b1    = (const float*)d_in[2];
    const float* W2    = (const float*)d_in[3];
    const float* b2    = (const float*)d_in[4];
    const int* eidx    = (const int*)d_in[5];     // [2, N_EDGES]
    const int* edges   = (const int*)d_in[6];     // [N_PAIRS, 2]
    const int* edgesn  = (const int*)d_in[7];
    float* out = (float*)d_out;

    const int* src = eidx;
    const int* dst = eidx + N_EDGES;

    float* deg; cudaGetSymbolAddress((void**)&deg, g_deg);
    float* t;   cudaGetSymbolAddress((void**)&t,   g_t);
    float* acc; cudaGetSymbolAddress((void**)&acc, g_acc);
    float* h;   cudaGetSymbolAddress((void**)&h,   g_h);

    // degrees + dinv
    k_init_deg<<<(N_NODES + 255) / 256, 256>>>(deg);
    k_deg<<<(N_EDGES + 255) / 256, 256>>>(dst, deg);
    k_dinv<<<(N_NODES + 255) / 256, 256>>>(deg);

    const int gemm_blocks = (N_NODES + 127) / 128;
    const int spmm_blocks = (N_EDGES * 32 + 255) / 256;
    const int fin_blocks  = (N_NODES * 32 + 255) / 256;

    // conv1: t = x@W1 ; acc = scatter ; h = relu(acc + t*dinv^2 + b1)
    k_gemm<<<gemm_blocks, 256>>>(x, W1, t, N_NODES);
    k_spmm<<<spmm_blocks, 256>>>(src, dst, deg, t, acc);
    k_finalize<true><<<fin_blocks, 256>>>(t, acc, deg, b1, h);

    // conv2: t = h@W2 ; acc = scatter ; h = acc + t*dinv^2 + b2
    k_gemm<<<gemm_blocks, 256>>>(h, W2, t, N_NODES);
    k_spmm<<<spmm_blocks, 256>>>(src, dst, deg, t, acc);
    k_finalize<false><<<fin_blocks, 256>>>(t, acc, deg, b2, h);

    // link prediction scores
    k_pairs<<<(2 * N_PAIRS * 32 + 255) / 256, 256>>>(edges, edgesn, h, out);
}

// round 2
// speedup vs baseline: 1.5143x; 1.5143x over previous
#include <cuda_runtime.h>
#include <cuda_bf16.h>
#include <math.h>

#define N_NODES 100000
#define N_EDGES 1600000
#define N_PAIRS 500000
#define D 128
#define SCAN_BLK 256
#define N_SBLK ((N_NODES + SCAN_BLK - 1) / SCAN_BLK)   // 391

// Scratch (device globals; no allocation allowed).
__device__ int   g_cnt[N_NODES];
__device__ float g_dinv[N_NODES];
__device__ int   g_offs[N_NODES];
__device__ int   g_rowptr[N_NODES + 1];
__device__ int   g_cursor[N_NODES];
__device__ int   g_bsum[512];
__device__ int   g_csr[N_EDGES];
__device__ float g_t[(size_t)N_NODES * D];
__device__ float g_h[(size_t)N_NODES * D];

// ---------------------------------------------------------------------------
// degree / CSR build
// ---------------------------------------------------------------------------
__global__ void k_zero_cnt(int* cnt) {
    int i = blockIdx.x * blockDim.x + threadIdx.x;
    if (i < N_NODES) cnt[i] = 0;
}

__global__ void k_count(const int* __restrict__ dst, int* cnt) {
    int e = blockIdx.x * blockDim.x + threadIdx.x;
    if (e < N_EDGES) atomicAdd(&cnt[dst[e]], 1);
}

__global__ void k_dinv(const int* __restrict__ cnt, float* dinv) {
    int i = blockIdx.x * blockDim.x + threadIdx.x;
    if (i < N_NODES) dinv[i] = rsqrtf((float)cnt[i] + 1.0f);  // +1 self loop
}

// exclusive scan of cnt -> offs (3 kernels)
__global__ void k_scan1(const int* __restrict__ cnt, int* offs, int* bsum) {
    __shared__ int sh[SCAN_BLK];
    int i = blockIdx.x * SCAN_BLK + threadIdx.x;
    int v = (i < N_NODES) ? cnt[i] : 0;
    sh[threadIdx.x] = v;
    __syncthreads();
#pragma unroll
    for (int off = 1; off < SCAN_BLK; off <<= 1) {
        int t = (threadIdx.x >= off) ? sh[threadIdx.x - off] : 0;
        __syncthreads();
        sh[threadIdx.x] += t;
        __syncthreads();
    }
    if (i < N_NODES) offs[i] = sh[threadIdx.x] - v;  // exclusive within block
    if (threadIdx.x == SCAN_BLK - 1) bsum[blockIdx.x] = sh[SCAN_BLK - 1];
}

__global__ void k_scan2(int* bsum) {  // single block, 512 threads (N_SBLK=391)
    __shared__ int sh[512];
    int v = (threadIdx.x < N_SBLK) ? bsum[threadIdx.x] : 0;
    sh[threadIdx.x] = v;
    __syncthreads();
#pragma unroll
    for (int off = 1; off < 512; off <<= 1) {
        int t = (threadIdx.x >= off) ? sh[threadIdx.x - off] : 0;
        __syncthreads();
        sh[threadIdx.x] += t;
        __syncthreads();
    }
    if (threadIdx.x < N_SBLK) bsum[threadIdx.x] = sh[threadIdx.x] - v;  // exclusive
}

__global__ void k_scan3(const int* __restrict__ offs, const int* __restrict__ bsum,
                        int* rowptr, int* cursor) {
    int i = blockIdx.x * SCAN_BLK + threadIdx.x;
    if (i < N_NODES) {
        int o = offs[i] + bsum[blockIdx.x];
        rowptr[i] = o;
        cursor[i] = o;
    }
    if (i == 0) rowptr[N_NODES] = N_EDGES;
}

__global__ void k_csr(const int* __restrict__ src, const int* __restrict__ dst,
                      int* cursor, int* csr_src) {
    int e = blockIdx.x * blockDim.x + threadIdx.x;
    if (e < N_EDGES) {
        int d = dst[e];
        int p = atomicAdd(&cursor[d], 1);
        csr_src[p] = src[e];
    }
}

// ---------------------------------------------------------------------------
// GEMM: C[M,128] = A[M,128] @ W[128,128]; 128x128 tile, double-buffered KC=32.
// ---------------------------------------------------------------------------
#define KC 32

static __device__ __forceinline__ void gemm_load(const float* __restrict__ A,
                                                 const float* __restrict__ W,
                                                 float (*As)[KC + 1], float (*Ws)[D],
                                                 int row0, int k0, int tid, int M) {
#pragma unroll
    for (int i = 0; i < 4; i++) {
        int f = tid + i * 256;   // 0..1023
        int r = f >> 3;          // 8 float4 per row
        int c4 = f & 7;
        float4 v = make_float4(0.f, 0.f, 0.f, 0.f);
        int gr = row0 + r;
        if (gr < M) v = *(const float4*)&A[(size_t)gr * D + k0 + c4 * 4];
        As[r][c4 * 4 + 0] = v.x;
        As[r][c4 * 4 + 1] = v.y;
        As[r][c4 * 4 + 2] = v.z;
        As[r][c4 * 4 + 3] = v.w;
    }
#pragma unroll
    for (int i = 0; i < 4; i++) {
        int f = tid + i * 256;
        int r = f >> 5;          // 32 float4 per row
        int c4 = f & 31;
        *(float4*)&Ws[r][c4 * 4] = *(const float4*)&W[(size_t)(k0 + r) * D + c4 * 4];
    }
}

__global__ __launch_bounds__(256, 2) void k_gemm(const float* __restrict__ A,
                                                 const float* __restrict__ W,
                                                 float* __restrict__ C, int M) {
    __shared__ float As[2][128][KC + 1];
    __shared__ float Ws[2][KC][D];

    int tid = threadIdx.x;
    int tx = tid & 15;
    int ty = tid >> 4;
    int row0 = blockIdx.x * 128;

    float acc[8][8];
#pragma unroll
    for (int i = 0; i < 8; i++)
#pragma unroll
        for (int j = 0; j < 8; j++) acc[i][j] = 0.0f;

    gemm_load(A, W, As[0], Ws[0], row0, 0, tid, M);
    __syncthreads();

#pragma unroll
    for (int c = 0; c < D / KC; c++) {
        if (c < D / KC - 1)
            gemm_load(A, W, As[(c + 1) & 1], Ws[(c + 1) & 1], row0, (c + 1) * KC, tid, M);
        int buf = c & 1;
#pragma unroll
        for (int kk = 0; kk < KC; kk++) {
            float a[8], b[8];
#pragma unroll
            for (int i = 0; i < 8; i++) a[i] = As[buf][ty * 8 + i][kk];
            float4 b0 = *(float4*)&Ws[buf][kk][tx * 8];
            float4 b1 = *(float4*)&Ws[buf][kk][tx * 8 + 4];
            b[0] = b0.x; b[1] = b0.y; b[2] = b0.z; b[3] = b0.w;
            b[4] = b1.x; b[5] = b1.y; b[6] = b1.z; b[7] = b1.w;
#pragma unroll
            for (int i = 0; i < 8; i++)
#pragma unroll
                for (int j = 0; j < 8; j++)
                    acc[i][j] = fmaf(a[i], b[j], acc[i][j]);
        }
        __syncthreads();
    }

#pragma unroll
    for (int i = 0; i < 8; i++) {
        int gr = row0 + ty * 8 + i;
        if (gr < M) {
            *(float4*)&C[(size_t)gr * D + tx * 8] =
                make_float4(acc[i][0], acc[i][1], acc[i][2], acc[i][3]);
            *(float4*)&C[(size_t)gr * D + tx * 8 + 4] =
                make_float4(acc[i][4], acc[i][5], acc[i][6], acc[i][7]);
        }
    }
}

// ---------------------------------------------------------------------------
// Fused gather-aggregate + self-loop + bias (+relu): warp per node.
// h[n] = act( sum_{s in N(n)} t[s]*dinv[s]*dinv[n] + t[n]*dinv[n]^2 + bias )
// ---------------------------------------------------------------------------
template <bool RELU>
__global__ __launch_bounds__(256) void k_aggregate(const int* __restrict__ rowptr,
                                                   const int* __restrict__ csr_src,
                                                   const float* __restrict__ dinv,
                                                   const float* __restrict__ t,
                                                   const float* __restrict__ bias,
                                                   float* __restrict__ h) {
    int node = (blockIdx.x * blockDim.x + threadIdx.x) >> 5;
    if (node >= N_NODES) return;
    int lane = threadIdx.x & 31;

    float di = __ldg(&dinv[node]);
    float s = di * di;
    float4 tv = *(const float4*)&t[(size_t)node * D + lane * 4];
    float4 acc;
    acc.x = tv.x * s; acc.y = tv.y * s; acc.z = tv.z * s; acc.w = tv.w * s;

    int beg = __ldg(&rowptr[node]);
    int end = __ldg(&rowptr[node + 1]);
    int i = beg;
    for (; i + 1 < end; i += 2) {
        int s0 = __ldg(&csr_src[i]);
        int s1 = __ldg(&csr_src[i + 1]);
        float n0 = __ldg(&dinv[s0]) * di;
        float n1 = __ldg(&dinv[s1]) * di;
        float4 v0 = *(const float4*)&t[(size_t)s0 * D + lane * 4];
        float4 v1 = *(const float4*)&t[(size_t)s1 * D + lane * 4];
        acc.x = fmaf(v0.x, n0, acc.x); acc.y = fmaf(v0.y, n0, acc.y);
        acc.z = fmaf(v0.z, n0, acc.z); acc.w = fmaf(v0.w, n0, acc.w);
        acc.x = fmaf(v1.x, n1, acc.x); acc.y = fmaf(v1.y, n1, acc.y);
        acc.z = fmaf(v1.z, n1, acc.z); acc.w = fmaf(v1.w, n1, acc.w);
    }
    if (i < end) {
        int s0 = __ldg(&csr_src[i]);
        float n0 = __ldg(&dinv[s0]) * di;
        float4 v0 = *(const float4*)&t[(size_t)s0 * D + lane * 4];
        acc.x = fmaf(v0.x, n0, acc.x); acc.y = fmaf(v0.y, n0, acc.y);
        acc.z = fmaf(v0.z, n0, acc.z); acc.w = fmaf(v0.w, n0, acc.w);
    }

    float4 b = *(const float4*)&bias[lane * 4];
    acc.x += b.x; acc.y += b.y; acc.z += b.z; acc.w += b.w;
    if (RELU) {
        acc.x = fmaxf(acc.x, 0.f); acc.y = fmaxf(acc.y, 0.f);
        acc.z = fmaxf(acc.z, 0.f); acc.w = fmaxf(acc.w, 0.f);
    }
    *(float4*)&h[(size_t)node * D + lane * 4] = acc;
}

// ---------------------------------------------------------------------------
// Pair scores: out[p] = dot(h[a], h[b]); warp per pair; pos then neg.
// ---------------------------------------------------------------------------
__global__ __launch_bounds__(256) void k_pairs(const int* __restrict__ edges,
                                               const int* __restrict__ edges_neg,
                                               const float* __restrict__ h,
                                               float* __restrict__ out) {
    int p = (blockIdx.x * blockDim.x + threadIdx.x) >> 5;
    if (p >= 2 * N_PAIRS) return;
    int lane = threadIdx.x & 31;
    const int* e = (p < N_PAIRS) ? edges : edges_neg;
    int pp = (p < N_PAIRS) ? p : (p - N_PAIRS);
    int a = __ldg(&e[2 * pp]);
    int b = __ldg(&e[2 * pp + 1]);
    float4 va = *(const float4*)&h[(size_t)a * D + lane * 4];
    float4 vb = *(const float4*)&h[(size_t)b * D + lane * 4];
    float sum = va.x * vb.x + va.y * vb.y + va.z * vb.z + va.w * vb.w;
#pragma unroll
    for (int off = 16; off > 0; off >>= 1)
        sum += __shfl_xor_sync(0xFFFFFFFFu, sum, off);
    if (lane == 0) out[p] = sum;
}

// ---------------------------------------------------------------------------
// launch
// ---------------------------------------------------------------------------
extern "C" void kernel_launch(void* const* d_in, const int* in_sizes, int n_in,
                              void* d_out, int out_size) {
    const float* x     = (const float*)d_in[0];
    const float* W1    = (const float*)d_in[1];
    const float* b1    = (const float*)d_in[2];
    const float* W2    = (const float*)d_in[3];
    const float* b2    = (const float*)d_in[4];
    const int* eidx    = (const int*)d_in[5];     // [2, N_EDGES]
    const int* edges   = (const int*)d_in[6];     // [N_PAIRS, 2]
    const int* edgesn  = (const int*)d_in[7];
    float* out = (float*)d_out;

    const int* src = eidx;
    const int* dst = eidx + N_EDGES;

    int*   cnt;    cudaGetSymbolAddress((void**)&cnt,    g_cnt);
    float* dinv;   cudaGetSymbolAddress((void**)&dinv,   g_dinv);
    int*   offs;   cudaGetSymbolAddress((void**)&offs,   g_offs);
    int*   rowptr; cudaGetSymbolAddress((void**)&rowptr, g_rowptr);
    int*   cursor; cudaGetSymbolAddress((void**)&cursor, g_cursor);
    int*   bsum;   cudaGetSymbolAddress((void**)&bsum,   g_bsum);
    int*   csr;    cudaGetSymbolAddress((void**)&csr,    g_csr);
    float* t;      cudaGetSymbolAddress((void**)&t,      g_t);
    float* h;      cudaGetSymbolAddress((void**)&h,      g_h);

    const int nodeb = (N_NODES + 255) / 256;
    const int edgeb = (N_EDGES + 255) / 256;

    // degree + CSR build (counting sort by dst)
    k_zero_cnt<<<nodeb, 256>>>(cnt);
    k_count<<<edgeb, 256>>>(dst, cnt);
    k_dinv<<<nodeb, 256>>>(cnt, dinv);
    k_scan1<<<N_SBLK, SCAN_BLK>>>(cnt, offs, bsum);
    k_scan2<<<1, 512>>>(bsum);
    k_scan3<<<N_SBLK, SCAN_BLK>>>(offs, bsum, rowptr, cursor);
    k_csr<<<edgeb, 256>>>(src, dst, cursor, csr);

    const int gemm_blocks = (N_NODES + 127) / 128;
    const int agg_blocks  = (N_NODES * 32 + 255) / 256;

    // conv1
    k_gemm<<<gemm_blocks, 256>>>(x, W1, t, N_NODES);
    k_aggregate<true><<<agg_blocks, 256>>>(rowptr, csr, dinv, t, b1, h);
    // conv2
    k_gemm<<<gemm_blocks, 256>>>(h, W2, t, N_NODES);
    k_aggregate<false><<<agg_blocks, 256>>>(rowptr, csr, dinv, t, b2, h);

    // link prediction scores
    k_pairs<<<(2 * N_PAIRS * 32 + 255) / 256, 256>>>(edges, edgesn, h, out);
}